// round 2
// baseline (speedup 1.0000x reference)
#include <cuda_runtime.h>

#define NN 2048
#define BB 32
#define TT 512
#define NT 16            // n-rows per CTA
#define GRIDSZ 128       // 128 CTAs * 16 rows = 2048
#define NTHR 256
#define KPAD 1026        // float2 per J smem row (2048/2 + pad 2)

#define F_DT   1e-4f
#define F_U    0.3f
#define F_TAU  0.008f
#define F_TAUF 1.5f
#define F_TAUD 0.3f
#define F_ALPHA 1.5f
#define F_IB   8.0f
#define F_JEI  1.1f
#define F_JIE  2.2f

// ---- persistent device state (double-buffered across steps) ----
__device__ float g_uxR[2][BB][NN];            // u*x*R(h), layout [b][m]
__device__ float g_partialSumR[2][GRIDSZ][BB];// per-CTA partial of sum_n R(h)
__device__ float g_partialOut[2][GRIDSZ][BB]; // per-CTA partial of readout
__device__ unsigned g_barCount;
__device__ unsigned g_barGen;

// packed fp32x2 fma: d = a*b + c elementwise (sm_100+)
__device__ __forceinline__ float2 ffma2(float2 a, float2 b, float2 c) {
    float2 d;
    asm("{\n\t"
        ".reg .b64 ra, rb, rc, rd;\n\t"
        "mov.b64 ra, {%2, %3};\n\t"
        "mov.b64 rb, {%4, %5};\n\t"
        "mov.b64 rc, {%6, %7};\n\t"
        "fma.rn.f32x2 rd, ra, rb, rc;\n\t"
        "mov.b64 {%0, %1}, rd;\n\t"
        "}"
        : "=f"(d.x), "=f"(d.y)
        : "f"(a.x), "f"(a.y), "f"(b.x), "f"(b.y), "f"(c.x), "f"(c.y));
    return d;
}

// R(h) = alpha * softplus(h/alpha), numerically stable
__device__ __forceinline__ float rate_fn(float h) {
    float z = h * (1.0f / F_ALPHA);
    float sp = fmaxf(z, 0.0f) + log1pf(expf(-fabsf(z)));
    return F_ALPHA * sp;
}

__global__ void init_kernel() {
    int i = blockIdx.x * blockDim.x + threadIdx.x;
    int stride = gridDim.x * blockDim.x;
    const float R0 = F_ALPHA * 0.6931471805599453f;  // rate(0)
    const float v = F_U * R0;                        // u0*x0*R0
    float* u0p = &g_uxR[0][0][0];
    for (int k = i; k < BB * NN; k += stride) u0p[k] = v;
    float* ps = &g_partialSumR[0][0][0];
    for (int k = i; k < GRIDSZ * BB; k += stride) ps[k] = (float)NT * R0;
    if (i == 0) { g_barCount = 0u; g_barGen = 0u; }
}

// software grid barrier: release fence + arrive; acquire fence after wait
__device__ __forceinline__ void gridSync() {
    __threadfence();
    __syncthreads();
    if (threadIdx.x == 0) {
        unsigned gen = *((volatile unsigned*)&g_barGen);
        unsigned ticket = atomicAdd(&g_barCount, 1u);
        if (ticket == gridDim.x - 1u) {
            g_barCount = 0u;
            __threadfence();
            atomicExch(&g_barGen, gen + 1u);
        } else {
            while (*((volatile unsigned*)&g_barGen) == gen) { }
        }
    }
    __syncthreads();
    __threadfence();   // invalidate L1D so post-barrier LDGs see fresh data
}

__global__ void __launch_bounds__(NTHR, 1)
step_kernel(const float* __restrict__ inp, const float* __restrict__ W_in,
            const float* __restrict__ J,   const float* __restrict__ W_out,
            float* __restrict__ out)
{
    extern __shared__ float smem[];
    float2* Jsd    = (float2*)smem;                 // [NT][KPAD] float2
    float*  redf   = smem + (size_t)NT * KPAD * 2;  // [8][16][32]
    float*  sPartA = redf + 8 * NT * BB;            // [8][32]
    float*  sPartB = sPartA + 8 * BB;               // [8][32]
    float*  shI    = sPartB + 8 * BB;               // [32]
    float*  sRI    = shI + BB;                      // [32]

    float* all_h  = out;
    float* all_u  = out + (size_t)TT * BB * NN;
    float* all_x  = out + (size_t)2 * TT * BB * NN;
    float* all_hI = out + (size_t)3 * TT * BB * NN;
    float* outputs = all_hI + (size_t)TT * BB;

    const int tid  = threadIdx.x;
    const int bid  = blockIdx.x;
    const int warp = tid >> 5;
    const int lane = tid & 31;
    const int ng   = lane >> 3;        // 0..3  n-group
    const int bpg  = lane & 7;         // 0..7  batch-group (4 batches each)
    const int n0   = bid * NT;

    // update-phase mapping: (batch ub, n-pair at n0 + unp*2)
    const int ub  = tid >> 3;          // 0..31
    const int unp = tid & 7;           // 0..7

    const float invTau  = 1.0f / F_TAU;
    const float invTauF = 1.0f / F_TAUF;
    const float invTauD = 1.0f / F_TAUD;

    // ---- stage J for this CTA's 16 rows ONCE (J is step-invariant) ----
    #pragma unroll 4
    for (int it = 0; it < 32; ++it) {
        int idx = tid + it * NTHR;     // 0..8191 (16 rows * 512 float4)
        int r   = idx >> 9;
        int c4  = idx & 511;
        float4 v = *(const float4*)(J + (size_t)(n0 + r) * NN + c4 * 4);
        *(float4*)(Jsd + (size_t)r * KPAD + c4 * 2) = v;
    }

    // preload per-thread constants
    const float wi0 = W_in[n0 + unp * 2];
    const float wi1 = W_in[n0 + unp * 2 + 1];
    const float wo0 = W_out[n0 + unp * 2];
    const float wo1 = W_out[n0 + unp * 2 + 1];

    if (tid < BB) shI[tid] = 0.0f;
    __syncthreads();

    // per-thread state registers
    float h0r = 0.0f, h1r = 0.0f;
    float u0r = F_U,  u1r = F_U;
    float x0r = 1.0f, x1r = 1.0f;

    const int cgrp = tid >> 5;         // 0..7 (reduction c-group)
    const int bred = tid & 31;         // batch for reductions

    for (int t = 0; t < TT; ++t) {
        const int cur = t & 1, nxt = cur ^ 1;

        // ================= GEMM: syn partials over this warp's 256 m =====
        const float* uxCur = &g_uxR[cur][0][0];
        const float* ubase = uxCur + warp * 256;
        const float2* jbase = Jsd + (size_t)(ng * 4) * KPAD + warp * 128;

        float2 acc[4][4];
        #pragma unroll
        for (int i = 0; i < 4; ++i)
            #pragma unroll
            for (int j = 0; j < 4; ++j) acc[i][j] = make_float2(0.f, 0.f);

        #pragma unroll 4
        for (int mi = 0; mi < 64; ++mi) {
            int mo = mi * 4;
            float4 u4[4], j4[4];
            #pragma unroll
            for (int j = 0; j < 4; ++j)
                u4[j] = *(const float4*)(ubase + (size_t)(bpg * 4 + j) * NN + mo);
            #pragma unroll
            for (int i = 0; i < 4; ++i)
                j4[i] = *(const float4*)(jbase + (size_t)i * KPAD + mi * 2);
            #pragma unroll
            for (int i = 0; i < 4; ++i) {
                float2 ja = make_float2(j4[i].x, j4[i].y);
                float2 jb = make_float2(j4[i].z, j4[i].w);
                #pragma unroll
                for (int j = 0; j < 4; ++j) {
                    acc[i][j] = ffma2(ja, make_float2(u4[j].x, u4[j].y), acc[i][j]);
                    acc[i][j] = ffma2(jb, make_float2(u4[j].z, u4[j].w), acc[i][j]);
                }
            }
        }

        // write per-warp partials: redf[warp][n_local][batch]
        #pragma unroll
        for (int i = 0; i < 4; ++i) {
            float4 p;
            p.x = acc[i][0].x + acc[i][0].y;
            p.y = acc[i][1].x + acc[i][1].y;
            p.z = acc[i][2].x + acc[i][2].y;
            p.w = acc[i][3].x + acc[i][3].y;
            *(float4*)&redf[warp * (NT * BB) + (ng * 4 + i) * BB + bpg * 4] = p;
        }

        // -------- C1: cross-CTA reductions of previous step's partials ---
        {
            float sA = 0.0f;
            const float* pS = &g_partialSumR[cur][0][0];
            #pragma unroll
            for (int c = 0; c < 16; ++c) sA += pS[(cgrp * 16 + c) * BB + bred];
            sPartA[cgrp * BB + bred] = sA;
            if (bid == 0 && t > 0) {
                float sB = 0.0f;
                const float* pO = &g_partialOut[cur][0][0];
                #pragma unroll
                for (int c = 0; c < 16; ++c) sB += pO[(cgrp * 16 + c) * BB + bred];
                sPartB[cgrp * BB + bred] = sB;
            }
        }
        __syncthreads();

        // -------- C2: h_I update (redundant per CTA), readout store ------
        if (tid < BB) {
            float tot = 0.0f;
            #pragma unroll
            for (int w = 0; w < 8; ++w) tot += sPartA[w * BB + tid];
            float hIold = shI[tid];
            sRI[tid] = rate_fn(hIold);
            float hI2 = hIold + (-hIold + F_JIE * tot) * invTau * F_DT;
            shI[tid] = hI2;
            if (bid == 0) {
                all_hI[(size_t)t * BB + tid] = hI2;
                if (t > 0) {
                    float totB = 0.0f;
                    #pragma unroll
                    for (int w = 0; w < 8; ++w) totB += sPartB[w * BB + tid];
                    outputs[(size_t)(t - 1) * BB + tid] = totB;
                }
            }
        }
        __syncthreads();

        // -------- C3: state update, outputs, next-step uxR/partials ------
        {
            float syn0 = 0.0f, syn1 = 0.0f;
            int base = (unp * 2) * BB + ub;
            #pragma unroll
            for (int w = 0; w < 8; ++w) {
                syn0 += redf[w * (NT * BB) + base];
                syn1 += redf[w * (NT * BB) + base + BB];
            }
            float RI = sRI[ub];
            float inval = inp[(size_t)t * BB + ub];
            float Ra = rate_fn(h0r);
            float Rb = rate_fn(h1r);

            float h2a = h0r + ((-h0r + syn0 + F_IB + inval * wi0) - F_JEI * RI) * invTau * F_DT;
            float h2b = h1r + ((-h1r + syn1 + F_IB + inval * wi1) - F_JEI * RI) * invTau * F_DT;
            float u2a = u0r + ((F_U - u0r) * invTauF + F_U * (1.0f - u0r) * Ra) * F_DT;
            float u2b = u1r + ((F_U - u1r) * invTauF + F_U * (1.0f - u1r) * Rb) * F_DT;
            float x2a = x0r + ((1.0f - x0r) * invTauD - u0r * x0r * Ra) * F_DT;
            float x2b = x1r + ((1.0f - x1r) * invTauD - u1r * x1r * Rb) * F_DT;

            size_t o = (size_t)t * (BB * NN) + (size_t)ub * NN + (n0 + unp * 2);
            *(float2*)&all_h[o] = make_float2(h2a, h2b);
            *(float2*)&all_u[o] = make_float2(u2a, u2b);
            *(float2*)&all_x[o] = make_float2(x2a, x2b);

            float R2a = rate_fn(h2a);
            float R2b = rate_fn(h2b);
            *(float2*)&g_uxR[nxt][ub][n0 + unp * 2] =
                make_float2(u2a * x2a * R2a, u2b * x2b * R2b);

            float sR = R2a + R2b;
            float sO = R2a * wo0 + R2b * wo1;
            #pragma unroll
            for (int d = 4; d > 0; d >>= 1) {
                sR += __shfl_xor_sync(0xFFFFFFFFu, sR, d, 8);
                sO += __shfl_xor_sync(0xFFFFFFFFu, sO, d, 8);
            }
            if ((tid & 7) == 0) {
                g_partialSumR[nxt][bid][ub] = sR;
                g_partialOut[nxt][bid][ub]  = sO;
            }

            h0r = h2a; h1r = h2b;
            u0r = u2a; u1r = u2b;
            x0r = x2a; x1r = x2b;
        }

        gridSync();
    }

    // -------- epilogue: readout for the final step (slot 0 = nxt(511)) ---
    if (bid == 0) {
        float sB = 0.0f;
        const float* pO = &g_partialOut[0][0][0];
        #pragma unroll
        for (int c = 0; c < 16; ++c) sB += pO[(cgrp * 16 + c) * BB + bred];
        sPartB[cgrp * BB + bred] = sB;
        __syncthreads();
        if (tid < BB) {
            float tot = 0.0f;
            #pragma unroll
            for (int w = 0; w < 8; ++w) tot += sPartB[w * BB + tid];
            outputs[(size_t)(TT - 1) * BB + tid] = tot;
        }
    }
}

#define SMEM_BYTES ((NT * KPAD * 2 + 8 * NT * BB + 8 * BB + 8 * BB + BB + BB) * 4)

extern "C" void kernel_launch(void* const* d_in, const int* in_sizes, int n_in,
                              void* d_out, int out_size) {
    const float* inp   = (const float*)d_in[0];
    const float* W_in  = (const float*)d_in[1];
    const float* J     = (const float*)d_in[2];
    const float* W_out = (const float*)d_in[3];
    float* out = (float*)d_out;

    cudaFuncSetAttribute(step_kernel, cudaFuncAttributeMaxDynamicSharedMemorySize,
                         SMEM_BYTES);
    init_kernel<<<64, 256>>>();
    step_kernel<<<GRIDSZ, NTHR, SMEM_BYTES>>>(inp, W_in, J, W_out, out);
}

// round 3
// speedup vs baseline: 2.8585x; 2.8585x over previous
#include <cuda_runtime.h>

#define NN 2048
#define BB 32
#define TT 512
#define NT 16            // n-rows per CTA
#define GRIDSZ 128       // 128 CTAs * 16 rows = 2048
#define NTHR 512
#define NWARP 16
#define MPW 128          // m-columns per warp (2048 / 16)
#define RPAD 33          // padded n-row stride in redf (bank-conflict-free)

#define F_DT   1e-4f
#define F_U    0.3f
#define F_TAU  0.008f
#define F_TAUF 1.5f
#define F_TAUD 0.3f
#define F_ALPHA 1.5f
#define F_IB   8.0f
#define F_JEI  1.1f
#define F_JIE  2.2f

// ---- persistent device state (double-buffered across steps) ----
__device__ float g_uxR[2][NN][BB];            // u*x*R(h), layout [m][b] (coalesced reads)
__device__ float g_partialSumR[2][GRIDSZ][BB];// per-CTA partial of sum_n R(h)
__device__ float g_partialOut[2][GRIDSZ][BB]; // per-CTA partial of readout
__device__ unsigned g_barCount;
__device__ unsigned g_barGen;

// packed fp32x2 fma: d = a*b + c elementwise (sm_100+)
__device__ __forceinline__ float2 ffma2(float2 a, float2 b, float2 c) {
    float2 d;
    asm("{\n\t"
        ".reg .b64 ra, rb, rc, rd;\n\t"
        "mov.b64 ra, {%2, %3};\n\t"
        "mov.b64 rb, {%4, %5};\n\t"
        "mov.b64 rc, {%6, %7};\n\t"
        "fma.rn.f32x2 rd, ra, rb, rc;\n\t"
        "mov.b64 {%0, %1}, rd;\n\t"
        "}"
        : "=f"(d.x), "=f"(d.y)
        : "f"(a.x), "f"(a.y), "f"(b.x), "f"(b.y), "f"(c.x), "f"(c.y));
    return d;
}

// R(h) = alpha * softplus(h/alpha), numerically stable
__device__ __forceinline__ float rate_fn(float h) {
    float z = h * (1.0f / F_ALPHA);
    float sp = fmaxf(z, 0.0f) + log1pf(expf(-fabsf(z)));
    return F_ALPHA * sp;
}

__global__ void init_kernel() {
    int i = blockIdx.x * blockDim.x + threadIdx.x;
    int stride = gridDim.x * blockDim.x;
    const float R0 = F_ALPHA * 0.6931471805599453f;  // rate(0)
    const float v = F_U * R0;                        // u0*x0*R0
    float* u0p = &g_uxR[0][0][0];
    for (int k = i; k < NN * BB; k += stride) u0p[k] = v;
    float* ps = &g_partialSumR[0][0][0];
    for (int k = i; k < GRIDSZ * BB; k += stride) ps[k] = (float)NT * R0;
    if (i == 0) { g_barCount = 0u; g_barGen = 0u; }
}

// software grid barrier: release fence + arrive; acquire fence after wait
__device__ __forceinline__ void gridSync() {
    __threadfence();
    __syncthreads();
    if (threadIdx.x == 0) {
        unsigned gen = *((volatile unsigned*)&g_barGen);
        unsigned ticket = atomicAdd(&g_barCount, 1u);
        if (ticket == gridDim.x - 1u) {
            g_barCount = 0u;
            __threadfence();
            atomicExch(&g_barGen, gen + 1u);
        } else {
            while (*((volatile unsigned*)&g_barGen) == gen) { }
        }
    }
    __syncthreads();
    __threadfence();   // invalidate L1D so post-barrier LDGs see fresh data
}

__global__ void __launch_bounds__(NTHR, 1)
step_kernel(const float* __restrict__ inp, const float* __restrict__ W_in,
            const float* __restrict__ J,   const float* __restrict__ W_out,
            float* __restrict__ out)
{
    extern __shared__ float smem[];
    float*  Jt     = smem;                          // [NN][NT] transposed J slice
    float*  redf   = Jt + (size_t)NN * NT;          // [NWARP][NT(pad RPAD)][BB]->[w][n*RPAD? no: w*NT*RPAD? see below]
    float*  sPartA = redf + (size_t)NWARP * NT * RPAD; // [NWARP][BB]
    float*  sPartB = sPartA + NWARP * BB;           // [NWARP][BB]
    float*  shI    = sPartB + NWARP * BB;           // [BB]
    float*  sRI    = shI + BB;                      // [BB]

    float* all_h  = out;
    float* all_u  = out + (size_t)TT * BB * NN;
    float* all_x  = out + (size_t)2 * TT * BB * NN;
    float* all_hI = out + (size_t)3 * TT * BB * NN;
    float* outputs = all_hI + (size_t)TT * BB;

    const int tid  = threadIdx.x;
    const int bid  = blockIdx.x;
    const int warp = tid >> 5;
    const int lane = tid & 31;
    const int n0   = bid * NT;

    // update-phase mapping: thread -> (batch ub, single neuron n0+un)
    const int ub = tid >> 4;           // 0..31
    const int un = tid & 15;           // 0..15

    const float invTau  = 1.0f / F_TAU;
    const float invTauF = 1.0f / F_TAUF;
    const float invTauD = 1.0f / F_TAUD;

    // ---- stage J transposed ONCE: Jt[m][n_local], m=0..2047, n_local=0..15
    #pragma unroll 4
    for (int it = 0; it < 16; ++it) {
        int idx = tid + it * NTHR;     // 0..8191 (16 rows * 512 float4)
        int r   = idx >> 9;            // 0..15
        int c4  = idx & 511;           // float4 col
        float4 v = *(const float4*)(J + (size_t)(n0 + r) * NN + c4 * 4);
        float* dst = Jt + (size_t)(c4 * 4) * NT + r;
        dst[0 * NT] = v.x;
        dst[1 * NT] = v.y;
        dst[2 * NT] = v.z;
        dst[3 * NT] = v.w;
    }

    const float wi = W_in[n0 + un];
    const float wo = W_out[n0 + un];

    if (tid < BB) shI[tid] = 0.0f;
    __syncthreads();

    // per-thread state
    float hr = 0.0f, ur = F_U, xr = 1.0f;

    for (int t = 0; t < TT; ++t) {
        const int cur = t & 1, nxt = cur ^ 1;

        // ================= GEMM: lane=batch, f32x2 over n-pairs ==========
        // warp handles m in [warp*MPW, (warp+1)*MPW)
        const float*  ubase = &g_uxR[cur][0][0] + (size_t)warp * MPW * BB + lane;
        const float4* Jt4   = (const float4*)Jt + (size_t)warp * MPW * (NT / 4);

        float2 acc[8];
        #pragma unroll
        for (int p = 0; p < 8; ++p) acc[p] = make_float2(0.f, 0.f);

        float uv[2][16];
        #pragma unroll
        for (int i = 0; i < 16; ++i) uv[0][i] = ubase[i * BB];   // prefetch chunk 0

        #pragma unroll 2
        for (int ch = 0; ch < 8; ++ch) {
            const int bufc = ch & 1, bufn = bufc ^ 1;
            if (ch < 7) {
                #pragma unroll
                for (int i = 0; i < 16; ++i)
                    uv[bufn][i] = ubase[((ch + 1) * 16 + i) * BB];
            }
            #pragma unroll
            for (int i = 0; i < 16; ++i) {
                const int m = ch * 16 + i;
                const float u = uv[bufc][i];
                const float2 uu = make_float2(u, u);
                float4 q0 = Jt4[m * 4 + 0];
                float4 q1 = Jt4[m * 4 + 1];
                float4 q2 = Jt4[m * 4 + 2];
                float4 q3 = Jt4[m * 4 + 3];
                acc[0] = ffma2(make_float2(q0.x, q0.y), uu, acc[0]);
                acc[1] = ffma2(make_float2(q0.z, q0.w), uu, acc[1]);
                acc[2] = ffma2(make_float2(q1.x, q1.y), uu, acc[2]);
                acc[3] = ffma2(make_float2(q1.z, q1.w), uu, acc[3]);
                acc[4] = ffma2(make_float2(q2.x, q2.y), uu, acc[4]);
                acc[5] = ffma2(make_float2(q2.z, q2.w), uu, acc[5]);
                acc[6] = ffma2(make_float2(q3.x, q3.y), uu, acc[6]);
                acc[7] = ffma2(make_float2(q3.z, q3.w), uu, acc[7]);
            }
        }

        // per-warp partials: redf[warp][n_local * RPAD? -> n stride RPAD][batch]
        {
            float* rw = redf + (size_t)warp * NT * RPAD + lane;
            #pragma unroll
            for (int p = 0; p < 8; ++p) {
                rw[(2 * p)     * RPAD] = acc[p].x;
                rw[(2 * p + 1) * RPAD] = acc[p].y;
            }
        }

        // -------- C1: cross-CTA reductions of previous step's partials ---
        {
            float sA = 0.0f;
            const float* pS = &g_partialSumR[cur][0][0];
            #pragma unroll
            for (int c = 0; c < 8; ++c) sA += pS[(warp * 8 + c) * BB + lane];
            sPartA[warp * BB + lane] = sA;
            if (bid == 0 && t > 0) {
                float sB = 0.0f;
                const float* pO = &g_partialOut[cur][0][0];
                #pragma unroll
                for (int c = 0; c < 8; ++c) sB += pO[(warp * 8 + c) * BB + lane];
                sPartB[warp * BB + lane] = sB;
            }
        }
        __syncthreads();

        // -------- C2: h_I update (redundant per CTA), readout store ------
        if (tid < BB) {
            float tot = 0.0f;
            #pragma unroll
            for (int w = 0; w < NWARP; ++w) tot += sPartA[w * BB + tid];
            float hIold = shI[tid];
            sRI[tid] = rate_fn(hIold);
            float hI2 = hIold + (-hIold + F_JIE * tot) * invTau * F_DT;
            shI[tid] = hI2;
            if (bid == 0) {
                all_hI[(size_t)t * BB + tid] = hI2;
                if (t > 0) {
                    float totB = 0.0f;
                    #pragma unroll
                    for (int w = 0; w < NWARP; ++w) totB += sPartB[w * BB + tid];
                    outputs[(size_t)(t - 1) * BB + tid] = totB;
                }
            }
        }
        __syncthreads();

        // -------- C3: state update, outputs, next-step uxR/partials ------
        {
            float syn = 0.0f;
            const float* rr = redf + un * RPAD + ub;
            #pragma unroll
            for (int w = 0; w < NWARP; ++w) syn += rr[w * NT * RPAD];

            float RI = sRI[ub];
            float inval = inp[(size_t)t * BB + ub];
            float R = rate_fn(hr);

            float h2 = hr + ((-hr + syn + F_IB + inval * wi) - F_JEI * RI) * invTau * F_DT;
            float u2 = ur + ((F_U - ur) * invTauF + F_U * (1.0f - ur) * R) * F_DT;
            float x2 = xr + ((1.0f - xr) * invTauD - ur * xr * R) * F_DT;

            size_t o = (size_t)t * (BB * NN) + (size_t)ub * NN + (n0 + un);
            all_h[o] = h2;
            all_u[o] = u2;
            all_x[o] = x2;

            float R2 = rate_fn(h2);
            g_uxR[nxt][n0 + un][ub] = u2 * x2 * R2;

            float sR = R2;
            float sO = R2 * wo;
            #pragma unroll
            for (int d = 8; d > 0; d >>= 1) {
                sR += __shfl_xor_sync(0xFFFFFFFFu, sR, d, 16);
                sO += __shfl_xor_sync(0xFFFFFFFFu, sO, d, 16);
            }
            if ((tid & 15) == 0) {
                g_partialSumR[nxt][bid][ub] = sR;
                g_partialOut[nxt][bid][ub]  = sO;
            }

            hr = h2; ur = u2; xr = x2;
        }

        gridSync();
    }

    // -------- epilogue: readout for the final step (buffer 0 = nxt(511)) -
    if (bid == 0) {
        float sB = 0.0f;
        const float* pO = &g_partialOut[0][0][0];
        #pragma unroll
        for (int c = 0; c < 8; ++c) sB += pO[(warp * 8 + c) * BB + lane];
        sPartB[warp * BB + lane] = sB;
        __syncthreads();
        if (tid < BB) {
            float tot = 0.0f;
            #pragma unroll
            for (int w = 0; w < NWARP; ++w) tot += sPartB[w * BB + tid];
            outputs[(size_t)(TT - 1) * BB + tid] = tot;
        }
    }
}

#define SMEM_FLOATS (NN * NT + NWARP * NT * RPAD + NWARP * BB + NWARP * BB + BB + BB)
#define SMEM_BYTES (SMEM_FLOATS * 4)

extern "C" void kernel_launch(void* const* d_in, const int* in_sizes, int n_in,
                              void* d_out, int out_size) {
    const float* inp   = (const float*)d_in[0];
    const float* W_in  = (const float*)d_in[1];
    const float* J     = (const float*)d_in[2];
    const float* W_out = (const float*)d_in[3];
    float* out = (float*)d_out;

    cudaFuncSetAttribute(step_kernel, cudaFuncAttributeMaxDynamicSharedMemorySize,
                         SMEM_BYTES);
    init_kernel<<<64, 256>>>();
    step_kernel<<<GRIDSZ, NTHR, SMEM_BYTES>>>(inp, W_in, J, W_out, out);
}

// round 4
// speedup vs baseline: 3.6566x; 1.2792x over previous
#include <cuda_runtime.h>

#define NN 2048
#define BB 32
#define TT 512
#define NT 16            // n-rows per CTA
#define GRIDSZ 128       // 128 CTAs * 16 rows = 2048
#define NTHR 512
#define NWARP 16
#define NSLICE 32        // 2 m-slices per warp
#define PADB 33          // padded batch stride (float2 units) in redp

#define F_DT   1e-4f
#define F_U    0.3f
#define F_TAU  0.008f
#define F_TAUF 1.5f
#define F_TAUD 0.3f
#define F_ALPHA 1.5f
#define F_IB   8.0f
#define F_JEI  1.1f
#define F_JIE  2.2f

// ---- persistent device state (double-buffered across steps) ----
__device__ float g_uxR[2][NN][BB];            // u*x*R(h), layout [m][b]
__device__ float g_partialSumR[2][GRIDSZ][BB];// per-CTA partial of sum_n R(h)
__device__ float g_partialOut[2][GRIDSZ][BB]; // per-CTA partial of readout
__device__ unsigned g_barCount;
__device__ unsigned g_barGen;

// packed fp32x2 fma: d = a*b + c elementwise (sm_100+)
__device__ __forceinline__ float2 ffma2(float2 a, float2 b, float2 c) {
    float2 d;
    asm("{\n\t"
        ".reg .b64 ra, rb, rc, rd;\n\t"
        "mov.b64 ra, {%2, %3};\n\t"
        "mov.b64 rb, {%4, %5};\n\t"
        "mov.b64 rc, {%6, %7};\n\t"
        "fma.rn.f32x2 rd, ra, rb, rc;\n\t"
        "mov.b64 {%0, %1}, rd;\n\t"
        "}"
        : "=f"(d.x), "=f"(d.y)
        : "f"(a.x), "f"(a.y), "f"(b.x), "f"(b.y), "f"(c.x), "f"(c.y));
    return d;
}

// R(h) = alpha * softplus(h/alpha), MUFU-based (fast, ~1e-6 rel err)
__device__ __forceinline__ float rate_fn(float h) {
    float z = h * (1.0f / F_ALPHA);
    float sp = fmaxf(z, 0.0f) + __logf(1.0f + __expf(-fabsf(z)));
    return F_ALPHA * sp;
}

__global__ void init_kernel() {
    int i = blockIdx.x * blockDim.x + threadIdx.x;
    int stride = gridDim.x * blockDim.x;
    const float R0 = F_ALPHA * 0.6931471805599453f;  // rate(0)
    const float v = F_U * R0;                        // u0*x0*R0
    float* u0p = &g_uxR[0][0][0];
    for (int k = i; k < NN * BB; k += stride) u0p[k] = v;
    float* ps = &g_partialSumR[0][0][0];
    for (int k = i; k < GRIDSZ * BB; k += stride) ps[k] = (float)NT * R0;
    if (i == 0) { g_barCount = 0u; g_barGen = 0u; }
}

// software grid barrier: release fence + arrive; acquire fence after wait
__device__ __forceinline__ void gridSync() {
    __threadfence();
    __syncthreads();
    if (threadIdx.x == 0) {
        unsigned gen = *((volatile unsigned*)&g_barGen);
        unsigned ticket = atomicAdd(&g_barCount, 1u);
        if (ticket == gridDim.x - 1u) {
            g_barCount = 0u;
            __threadfence();
            atomicExch(&g_barGen, gen + 1u);
        } else {
            while (*((volatile unsigned*)&g_barGen) == gen) { }
        }
    }
    __syncthreads();
    __threadfence();   // invalidate L1D so post-barrier LDGs see fresh data
}

__global__ void __launch_bounds__(NTHR, 1)
step_kernel(const float* __restrict__ inp, const float* __restrict__ W_in,
            const float* __restrict__ J,   const float* __restrict__ W_out,
            float* __restrict__ out)
{
    extern __shared__ float smem[];
    float*  Jt     = smem;                             // [NN][NT] transposed J slice
    float2* redp   = (float2*)(Jt + (size_t)NN * NT);  // [NSLICE][8 npair][PADB]
    float*  sPartA = (float*)(redp + (size_t)NSLICE * 8 * PADB); // [NWARP][BB]
    float*  sPartB = sPartA + NWARP * BB;              // [NWARP][BB]
    float*  shI    = sPartB + NWARP * BB;              // [BB]
    float*  sRI    = shI + BB;                         // [BB]

    float* all_h  = out;
    float* all_u  = out + (size_t)TT * BB * NN;
    float* all_x  = out + (size_t)2 * TT * BB * NN;
    float* all_hI = out + (size_t)3 * TT * BB * NN;
    float* outputs = all_hI + (size_t)TT * BB;

    const int tid  = threadIdx.x;
    const int bid  = blockIdx.x;
    const int warp = tid >> 5;
    const int lane = tid & 31;
    const int half = lane >> 4;        // 0..1 (m-stream within warp)
    const int bp   = lane & 15;        // batch pair: batches 2bp, 2bp+1
    const int n0   = bid * NT;
    const int slice = warp * 2 + half;

    // update-phase mapping: thread -> (batch ub, single neuron n0+un)
    const int ub = tid >> 4;           // 0..31
    const int un = tid & 15;           // 0..15

    const float invTau  = 1.0f / F_TAU;
    const float invTauF = 1.0f / F_TAUF;
    const float invTauD = 1.0f / F_TAUD;

    // ---- stage J transposed ONCE: Jt[m][n_local] ----
    #pragma unroll 4
    for (int it = 0; it < 16; ++it) {
        int idx = tid + it * NTHR;     // 0..8191 (16 rows * 512 float4)
        int r   = idx >> 9;            // 0..15
        int c4  = idx & 511;           // float4 col
        float4 v = *(const float4*)(J + (size_t)(n0 + r) * NN + c4 * 4);
        float* dst = Jt + (size_t)(c4 * 4) * NT + r;
        dst[0 * NT] = v.x;
        dst[1 * NT] = v.y;
        dst[2 * NT] = v.z;
        dst[3 * NT] = v.w;
    }

    const float wi = W_in[n0 + un];
    const float wo = W_out[n0 + un];

    if (tid < BB) shI[tid] = 0.0f;
    __syncthreads();

    // per-thread state
    float hr = 0.0f, ur = F_U, xr = 1.0f;

    // GEMM m index for iteration mi: m = warp*128 + 2*mi + half
    const int mbase = warp * 128 + half;

    for (int t = 0; t < TT; ++t) {
        const int cur = t & 1, nxt = cur ^ 1;

        // ===== GEMM: per-thread 2 batches x 16 n over 64 m ===============
        const float2* ub2 = (const float2*)&g_uxR[cur][0][0];  // [m][16] float2
        // u addr for mi: ub2[(mbase + 2*mi)*16 + bp]
        const float4* Jt4 = (const float4*)Jt;                 // [m][4] float4

        float2 acc[8][2];
        #pragma unroll
        for (int p = 0; p < 8; ++p) {
            acc[p][0] = make_float2(0.f, 0.f);
            acc[p][1] = make_float2(0.f, 0.f);
        }

        float2 uv[2][8];
        #pragma unroll
        for (int i = 0; i < 8; ++i)
            uv[0][i] = ub2[(size_t)(mbase + 2 * i) * 16 + bp];

        #pragma unroll 2
        for (int ch = 0; ch < 8; ++ch) {
            const int bufc = ch & 1, bufn = bufc ^ 1;
            if (ch < 7) {
                #pragma unroll
                for (int i = 0; i < 8; ++i)
                    uv[bufn][i] = ub2[(size_t)(mbase + 2 * ((ch + 1) * 8 + i)) * 16 + bp];
            }
            #pragma unroll
            for (int i = 0; i < 8; ++i) {
                const int m = mbase + 2 * (ch * 8 + i);
                const float2 u2 = uv[bufc][i];
                const float2 uu0 = make_float2(u2.x, u2.x);
                const float2 uu1 = make_float2(u2.y, u2.y);
                float4 q0 = Jt4[m * 4 + 0];
                float4 q1 = Jt4[m * 4 + 1];
                float4 q2 = Jt4[m * 4 + 2];
                float4 q3 = Jt4[m * 4 + 3];
                acc[0][0] = ffma2(make_float2(q0.x, q0.y), uu0, acc[0][0]);
                acc[0][1] = ffma2(make_float2(q0.x, q0.y), uu1, acc[0][1]);
                acc[1][0] = ffma2(make_float2(q0.z, q0.w), uu0, acc[1][0]);
                acc[1][1] = ffma2(make_float2(q0.z, q0.w), uu1, acc[1][1]);
                acc[2][0] = ffma2(make_float2(q1.x, q1.y), uu0, acc[2][0]);
                acc[2][1] = ffma2(make_float2(q1.x, q1.y), uu1, acc[2][1]);
                acc[3][0] = ffma2(make_float2(q1.z, q1.w), uu0, acc[3][0]);
                acc[3][1] = ffma2(make_float2(q1.z, q1.w), uu1, acc[3][1]);
                acc[4][0] = ffma2(make_float2(q2.x, q2.y), uu0, acc[4][0]);
                acc[4][1] = ffma2(make_float2(q2.x, q2.y), uu1, acc[4][1]);
                acc[5][0] = ffma2(make_float2(q2.z, q2.w), uu0, acc[5][0]);
                acc[5][1] = ffma2(make_float2(q2.z, q2.w), uu1, acc[5][1]);
                acc[6][0] = ffma2(make_float2(q3.x, q3.y), uu0, acc[6][0]);
                acc[6][1] = ffma2(make_float2(q3.x, q3.y), uu1, acc[6][1]);
                acc[7][0] = ffma2(make_float2(q3.z, q3.w), uu0, acc[7][0]);
                acc[7][1] = ffma2(make_float2(q3.z, q3.w), uu1, acc[7][1]);
            }
        }

        // partials: redp[slice][p][batch] (float2 over n-pair p)
        {
            float2* rw = redp + (size_t)slice * 8 * PADB + 2 * bp;
            #pragma unroll
            for (int p = 0; p < 8; ++p) {
                rw[p * PADB]     = acc[p][0];
                rw[p * PADB + 1] = acc[p][1];
            }
        }

        // -------- C1: cross-CTA reductions of previous step's partials ---
        {
            float sA = 0.0f;
            const float* pS = &g_partialSumR[cur][0][0];
            #pragma unroll
            for (int c = 0; c < 8; ++c) sA += pS[(warp * 8 + c) * BB + lane];
            sPartA[warp * BB + lane] = sA;
            if (bid == 0 && t > 0) {
                float sB = 0.0f;
                const float* pO = &g_partialOut[cur][0][0];
                #pragma unroll
                for (int c = 0; c < 8; ++c) sB += pO[(warp * 8 + c) * BB + lane];
                sPartB[warp * BB + lane] = sB;
            }
        }
        __syncthreads();

        // -------- C2: h_I update (redundant per CTA), readout store ------
        if (tid < BB) {
            float tot = 0.0f;
            #pragma unroll
            for (int w = 0; w < NWARP; ++w) tot += sPartA[w * BB + tid];
            float hIold = shI[tid];
            sRI[tid] = rate_fn(hIold);
            float hI2 = hIold + (-hIold + F_JIE * tot) * invTau * F_DT;
            shI[tid] = hI2;
            if (bid == 0) {
                all_hI[(size_t)t * BB + tid] = hI2;
                if (t > 0) {
                    float totB = 0.0f;
                    #pragma unroll
                    for (int w = 0; w < NWARP; ++w) totB += sPartB[w * BB + tid];
                    outputs[(size_t)(t - 1) * BB + tid] = totB;
                }
            }
        }
        __syncthreads();

        // -------- C3: state update, outputs, next-step uxR/partials ------
        {
            const int p = un >> 1, r = un & 1;
            float syn = 0.0f;
            const float2* rr = redp + (size_t)p * PADB + ub;
            if (r == 0) {
                #pragma unroll
                for (int s = 0; s < NSLICE; ++s) syn += rr[(size_t)s * 8 * PADB].x;
            } else {
                #pragma unroll
                for (int s = 0; s < NSLICE; ++s) syn += rr[(size_t)s * 8 * PADB].y;
            }

            float RI = sRI[ub];
            float inval = inp[(size_t)t * BB + ub];
            float R = rate_fn(hr);

            float h2 = hr + ((-hr + syn + F_IB + inval * wi) - F_JEI * RI) * invTau * F_DT;
            float u2 = ur + ((F_U - ur) * invTauF + F_U * (1.0f - ur) * R) * F_DT;
            float x2 = xr + ((1.0f - xr) * invTauD - ur * xr * R) * F_DT;

            size_t o = (size_t)t * (BB * NN) + (size_t)ub * NN + (n0 + un);
            all_h[o] = h2;
            all_u[o] = u2;
            all_x[o] = x2;

            float R2 = rate_fn(h2);
            g_uxR[nxt][n0 + un][ub] = u2 * x2 * R2;

            float sR = R2;
            float sO = R2 * wo;
            #pragma unroll
            for (int d = 8; d > 0; d >>= 1) {
                sR += __shfl_xor_sync(0xFFFFFFFFu, sR, d, 16);
                sO += __shfl_xor_sync(0xFFFFFFFFu, sO, d, 16);
            }
            if ((tid & 15) == 0) {
                g_partialSumR[nxt][bid][ub] = sR;
                g_partialOut[nxt][bid][ub]  = sO;
            }

            hr = h2; ur = u2; xr = x2;
        }

        gridSync();
    }

    // -------- epilogue: readout for the final step (buffer 0 = nxt(511)) -
    if (bid == 0) {
        float sB = 0.0f;
        const float* pO = &g_partialOut[0][0][0];
        #pragma unroll
        for (int c = 0; c < 8; ++c) sB += pO[(warp * 8 + c) * BB + lane];
        sPartB[warp * BB + lane] = sB;
        __syncthreads();
        if (tid < BB) {
            float tot = 0.0f;
            #pragma unroll
            for (int w = 0; w < NWARP; ++w) tot += sPartB[w * BB + tid];
            outputs[(size_t)(TT - 1) * BB + tid] = tot;
        }
    }
}

#define SMEM_BYTES ((NN * NT) * 4 + (NSLICE * 8 * PADB) * 8 + (NWARP * BB * 2 + BB * 2) * 4)

extern "C" void kernel_launch(void* const* d_in, const int* in_sizes, int n_in,
                              void* d_out, int out_size) {
    const float* inp   = (const float*)d_in[0];
    const float* W_in  = (const float*)d_in[1];
    const float* J     = (const float*)d_in[2];
    const float* W_out = (const float*)d_in[3];
    float* out = (float*)d_out;

    cudaFuncSetAttribute(step_kernel, cudaFuncAttributeMaxDynamicSharedMemorySize,
                         SMEM_BYTES);
    init_kernel<<<64, 256>>>();
    step_kernel<<<GRIDSZ, NTHR, SMEM_BYTES>>>(inp, W_in, J, W_out, out);
}

// round 5
// speedup vs baseline: 3.8221x; 1.0453x over previous
#include <cuda_runtime.h>

#define NN 2048
#define BB 32
#define TT 512
#define NT 16            // n-rows per CTA
#define GRIDSZ 128       // 128 CTAs * 16 rows = 2048
#define NTHR 512
#define NWARP 16
#define NSLICE 32        // 2 m-slices per warp
#define PADB 33          // padded batch stride (float2 units) in redp

#define F_DT   1e-4f
#define F_U    0.3f
#define F_TAU  0.008f
#define F_TAUF 1.5f
#define F_TAUD 0.3f
#define F_ALPHA 1.5f
#define F_IB   8.0f
#define F_JEI  1.1f
#define F_JIE  2.2f

typedef unsigned long long ull;

// ---- persistent device state (double-buffered across steps) ----
__device__ float g_uxR[2][NN][BB];            // u*x*R(h), layout [m][b]
__device__ float g_partialSumR[2][GRIDSZ][BB];// per-CTA partial of sum_n R(h)
__device__ float g_partialOut[2][GRIDSZ][BB]; // per-CTA partial of readout
__device__ unsigned g_barCount;               // monotonic arrival counter

// packed fp32x2 fma, accumulator form: d = a*b + d  (single FFMA2, no movs)
__device__ __forceinline__ void ffma2u(ull& d, ull a, ull b) {
    asm("fma.rn.f32x2 %0, %1, %2, %0;" : "+l"(d) : "l"(a), "l"(b));
}
__device__ __forceinline__ ull pack2(float v) {
    ull r; asm("mov.b64 %0, {%1, %1};" : "=l"(r) : "f"(v)); return r;
}
__device__ __forceinline__ float2 unpack2(ull v) {
    float2 r; asm("mov.b64 {%0, %1}, %2;" : "=f"(r.x), "=f"(r.y) : "l"(v)); return r;
}

// R(h) = alpha * softplus(h/alpha), MUFU-based
__device__ __forceinline__ float rate_fn(float h) {
    float z = h * (1.0f / F_ALPHA);
    float sp = fmaxf(z, 0.0f) + __logf(1.0f + __expf(-fabsf(z)));
    return F_ALPHA * sp;
}

__global__ void init_kernel() {
    int i = blockIdx.x * blockDim.x + threadIdx.x;
    int stride = gridDim.x * blockDim.x;
    const float R0 = F_ALPHA * 0.6931471805599453f;  // rate(0)
    const float v = F_U * R0;                        // u0*x0*R0
    float* u0p = &g_uxR[0][0][0];
    for (int k = i; k < NN * BB; k += stride) u0p[k] = v;
    float* ps = &g_partialSumR[0][0][0];
    for (int k = i; k < GRIDSZ * BB; k += stride) ps[k] = (float)NT * R0;
    if (i == 0) g_barCount = 0u;
}

// fence-free grid barrier: bar.sync (cta fence) + release-arrive + acquire-spin.
// Counter is monotonic: after step t all 128 CTAs have arrived (t+1) times.
__device__ __forceinline__ void gridSync(int t) {
    __syncthreads();
    if (threadIdx.x == 0) {
        asm volatile("red.release.gpu.global.add.u32 [%0], %1;"
                     :: "l"(&g_barCount), "r"(1u) : "memory");
        const unsigned target = (unsigned)(t + 1) * GRIDSZ;
        unsigned v;
        do {
            asm volatile("ld.acquire.gpu.global.u32 %0, [%1];"
                         : "=r"(v) : "l"(&g_barCount) : "memory");
        } while (v < target);
    }
    __syncthreads();
}

__global__ void __launch_bounds__(NTHR, 1)
step_kernel(const float* __restrict__ inp, const float* __restrict__ W_in,
            const float* __restrict__ J,   const float* __restrict__ W_out,
            float* __restrict__ out)
{
    extern __shared__ float smem[];
    float*  Jt     = smem;                             // [NN][NT] transposed J slice
    float2* redp   = (float2*)(Jt + (size_t)NN * NT);  // [NSLICE][8 npair][PADB]
    float*  sPartA = (float*)(redp + (size_t)NSLICE * 8 * PADB); // [NWARP][BB]
    float*  sPartB = sPartA + NWARP * BB;              // [NWARP][BB]
    float*  shI    = sPartB + NWARP * BB;              // [BB]
    float*  sRI    = shI + BB;                         // [BB]

    float* all_h  = out;
    float* all_u  = out + (size_t)TT * BB * NN;
    float* all_x  = out + (size_t)2 * TT * BB * NN;
    float* all_hI = out + (size_t)3 * TT * BB * NN;
    float* outputs = all_hI + (size_t)TT * BB;

    const int tid  = threadIdx.x;
    const int bid  = blockIdx.x;
    const int warp = tid >> 5;
    const int lane = tid & 31;
    const int half = lane >> 4;        // 0..1 (m-stream within warp)
    const int bp   = lane & 15;        // batch pair: batches 2bp, 2bp+1
    const int n0   = bid * NT;
    const int slice = warp * 2 + half;

    // update-phase mapping: thread -> (batch ub, single neuron n0+un)
    const int ub = tid >> 4;           // 0..31
    const int un = tid & 15;           // 0..15

    const float invTau  = 1.0f / F_TAU;
    const float invTauF = 1.0f / F_TAUF;
    const float invTauD = 1.0f / F_TAUD;

    // ---- stage J transposed ONCE: Jt[m][n_local] ----
    #pragma unroll 4
    for (int it = 0; it < 16; ++it) {
        int idx = tid + it * NTHR;     // 0..8191 (16 rows * 512 float4)
        int r   = idx >> 9;            // 0..15
        int c4  = idx & 511;           // float4 col
        float4 v = *(const float4*)(J + (size_t)(n0 + r) * NN + c4 * 4);
        float* dst = Jt + (size_t)(c4 * 4) * NT + r;
        dst[0 * NT] = v.x;
        dst[1 * NT] = v.y;
        dst[2 * NT] = v.z;
        dst[3 * NT] = v.w;
    }

    const float wi = W_in[n0 + un];
    const float wo = W_out[n0 + un];

    if (tid < BB) shI[tid] = 0.0f;
    __syncthreads();

    // per-thread state
    float hr = 0.0f, ur = F_U, xr = 1.0f;

    // GEMM m index for iteration mi: m = warp*128 + 2*mi + half
    const int mbase = warp * 128 + half;

    for (int t = 0; t < TT; ++t) {
        const int cur = t & 1, nxt = cur ^ 1;

        // ===== GEMM: per-thread 2 batches x 16 n over 64 m ===============
        const float2* ub2 = (const float2*)&g_uxR[cur][0][0];  // [m][16] float2
        const ulonglong2* Jt2 = (const ulonglong2*)Jt;         // [m][4] x 16B

        ull acc[8][2];
        #pragma unroll
        for (int p = 0; p < 8; ++p) { acc[p][0] = 0ull; acc[p][1] = 0ull; }

        float2 uv[2][8];
        #pragma unroll
        for (int i = 0; i < 8; ++i)
            uv[0][i] = __ldcg(ub2 + (size_t)(mbase + 2 * i) * 16 + bp);

        #pragma unroll 2
        for (int ch = 0; ch < 8; ++ch) {
            const int bufc = ch & 1, bufn = bufc ^ 1;
            if (ch < 7) {
                #pragma unroll
                for (int i = 0; i < 8; ++i)
                    uv[bufn][i] = __ldcg(ub2 + (size_t)(mbase + 2 * ((ch + 1) * 8 + i)) * 16 + bp);
            }
            #pragma unroll
            for (int i = 0; i < 8; ++i) {
                const int m = mbase + 2 * (ch * 8 + i);
                const float2 u2 = uv[bufc][i];
                const ull uu0 = pack2(u2.x);
                const ull uu1 = pack2(u2.y);
                ulonglong2 q0 = Jt2[m * 4 + 0];
                ulonglong2 q1 = Jt2[m * 4 + 1];
                ulonglong2 q2 = Jt2[m * 4 + 2];
                ulonglong2 q3 = Jt2[m * 4 + 3];
                ffma2u(acc[0][0], q0.x, uu0); ffma2u(acc[0][1], q0.x, uu1);
                ffma2u(acc[1][0], q0.y, uu0); ffma2u(acc[1][1], q0.y, uu1);
                ffma2u(acc[2][0], q1.x, uu0); ffma2u(acc[2][1], q1.x, uu1);
                ffma2u(acc[3][0], q1.y, uu0); ffma2u(acc[3][1], q1.y, uu1);
                ffma2u(acc[4][0], q2.x, uu0); ffma2u(acc[4][1], q2.x, uu1);
                ffma2u(acc[5][0], q2.y, uu0); ffma2u(acc[5][1], q2.y, uu1);
                ffma2u(acc[6][0], q3.x, uu0); ffma2u(acc[6][1], q3.x, uu1);
                ffma2u(acc[7][0], q3.y, uu0); ffma2u(acc[7][1], q3.y, uu1);
            }
        }

        // partials: redp[slice][p][batch] (float2 over n-pair p)
        {
            float2* rw = redp + (size_t)slice * 8 * PADB + 2 * bp;
            #pragma unroll
            for (int p = 0; p < 8; ++p) {
                rw[p * PADB]     = unpack2(acc[p][0]);
                rw[p * PADB + 1] = unpack2(acc[p][1]);
            }
        }

        // -------- C1: cross-CTA reductions of previous step's partials ---
        {
            float sA = 0.0f;
            const float* pS = &g_partialSumR[cur][0][0];
            #pragma unroll
            for (int c = 0; c < 8; ++c) sA += __ldcg(pS + (warp * 8 + c) * BB + lane);
            sPartA[warp * BB + lane] = sA;
            if (bid == 0 && t > 0) {
                float sB = 0.0f;
                const float* pO = &g_partialOut[cur][0][0];
                #pragma unroll
                for (int c = 0; c < 8; ++c) sB += __ldcg(pO + (warp * 8 + c) * BB + lane);
                sPartB[warp * BB + lane] = sB;
            }
        }
        __syncthreads();

        // -------- C2: h_I update (redundant per CTA), readout store ------
        if (tid < BB) {
            float tot = 0.0f;
            #pragma unroll
            for (int w = 0; w < NWARP; ++w) tot += sPartA[w * BB + tid];
            float hIold = shI[tid];
            sRI[tid] = rate_fn(hIold);
            float hI2 = hIold + (-hIold + F_JIE * tot) * invTau * F_DT;
            shI[tid] = hI2;
            if (bid == 0) {
                all_hI[(size_t)t * BB + tid] = hI2;
                if (t > 0) {
                    float totB = 0.0f;
                    #pragma unroll
                    for (int w = 0; w < NWARP; ++w) totB += sPartB[w * BB + tid];
                    outputs[(size_t)(t - 1) * BB + tid] = totB;
                }
            }
        }
        __syncthreads();

        // -------- C3: state update, outputs, next-step uxR/partials ------
        {
            const int p = un >> 1, r = un & 1;
            float syn = 0.0f;
            const float2* rr = redp + (size_t)p * PADB + ub;
            if (r == 0) {
                #pragma unroll
                for (int s = 0; s < NSLICE; ++s) syn += rr[(size_t)s * 8 * PADB].x;
            } else {
                #pragma unroll
                for (int s = 0; s < NSLICE; ++s) syn += rr[(size_t)s * 8 * PADB].y;
            }

            float RI = sRI[ub];
            float inval = inp[(size_t)t * BB + ub];
            float R = rate_fn(hr);

            float h2 = hr + ((-hr + syn + F_IB + inval * wi) - F_JEI * RI) * invTau * F_DT;
            float u2 = ur + ((F_U - ur) * invTauF + F_U * (1.0f - ur) * R) * F_DT;
            float x2 = xr + ((1.0f - xr) * invTauD - ur * xr * R) * F_DT;

            size_t o = (size_t)t * (BB * NN) + (size_t)ub * NN + (n0 + un);
            all_h[o] = h2;
            all_u[o] = u2;
            all_x[o] = x2;

            float R2 = rate_fn(h2);
            g_uxR[nxt][n0 + un][ub] = u2 * x2 * R2;

            float sR = R2;
            float sO = R2 * wo;
            #pragma unroll
            for (int d = 8; d > 0; d >>= 1) {
                sR += __shfl_xor_sync(0xFFFFFFFFu, sR, d, 16);
                sO += __shfl_xor_sync(0xFFFFFFFFu, sO, d, 16);
            }
            if ((tid & 15) == 0) {
                g_partialSumR[nxt][bid][ub] = sR;
                g_partialOut[nxt][bid][ub]  = sO;
            }

            hr = h2; ur = u2; xr = x2;
        }

        gridSync(t);
    }

    // -------- epilogue: readout for the final step (buffer 0 = nxt(511)) -
    if (bid == 0) {
        float sB = 0.0f;
        const float* pO = &g_partialOut[0][0][0];
        #pragma unroll
        for (int c = 0; c < 8; ++c) sB += __ldcg(pO + (warp * 8 + c) * BB + lane);
        sPartB[warp * BB + lane] = sB;
        __syncthreads();
        if (tid < BB) {
            float tot = 0.0f;
            #pragma unroll
            for (int w = 0; w < NWARP; ++w) tot += sPartB[w * BB + tid];
            outputs[(size_t)(TT - 1) * BB + tid] = tot;
        }
    }
}

#define SMEM_BYTES ((NN * NT) * 4 + (NSLICE * 8 * PADB) * 8 + (NWARP * BB * 2 + BB * 2) * 4)

extern "C" void kernel_launch(void* const* d_in, const int* in_sizes, int n_in,
                              void* d_out, int out_size) {
    const float* inp   = (const float*)d_in[0];
    const float* W_in  = (const float*)d_in[1];
    const float* J     = (const float*)d_in[2];
    const float* W_out = (const float*)d_in[3];
    float* out = (float*)d_out;

    cudaFuncSetAttribute(step_kernel, cudaFuncAttributeMaxDynamicSharedMemorySize,
                         SMEM_BYTES);
    init_kernel<<<64, 256>>>();
    step_kernel<<<GRIDSZ, NTHR, SMEM_BYTES>>>(inp, W_in, J, W_out, out);
}

// round 7
// speedup vs baseline: 4.1390x; 1.0829x over previous
#include <cuda_runtime.h>

#define NN 2048
#define BB 32
#define TT 512
#define NT 16            // n-rows per CTA
#define GRIDSZ 128       // 128 CTAs * 16 rows = 2048
#define NTHR 512
#define NWARP 16
#define NSLICE 16        // 1 reduced slice per warp (streams shfl-reduced)
#define PADB 34          // padded batch stride (float2 units) — EVEN for 16B stores
#define JSTR 20          // Jt row stride in floats (16 data + 4 pad)

#define F_DT   1e-4f
#define F_U    0.3f
#define F_TAU  0.008f
#define F_TAUF 1.5f
#define F_TAUD 0.3f
#define F_ALPHA 1.5f
#define F_IB   8.0f
#define F_JEI  1.1f
#define F_JIE  2.2f

typedef unsigned long long ull;

// ---- persistent device state (double-buffered across steps) ----
__device__ float g_uxR[2][NN][BB];            // u*x*R(h), layout [m][b]
__device__ float g_partialSumR[2][GRIDSZ][BB];// per-CTA partial of sum_n R(h)
__device__ float g_partialOut[2][GRIDSZ][BB]; // per-CTA partial of readout
__device__ unsigned g_barCount;               // monotonic arrival counter

// packed fp32x2 fma, accumulator form: d = a*b + d
__device__ __forceinline__ void ffma2u(ull& d, ull a, ull b) {
    asm("fma.rn.f32x2 %0, %1, %2, %0;" : "+l"(d) : "l"(a), "l"(b));
}
__device__ __forceinline__ ull pack2(float v) {
    ull r; asm("mov.b64 %0, {%1, %1};" : "=l"(r) : "f"(v)); return r;
}

// R(h) = alpha * softplus(h/alpha), MUFU-based
__device__ __forceinline__ float rate_fn(float h) {
    float z = h * (1.0f / F_ALPHA);
    float sp = fmaxf(z, 0.0f) + __logf(1.0f + __expf(-fabsf(z)));
    return F_ALPHA * sp;
}

__global__ void init_kernel() {
    int i = blockIdx.x * blockDim.x + threadIdx.x;
    int stride = gridDim.x * blockDim.x;
    const float R0 = F_ALPHA * 0.6931471805599453f;  // rate(0)
    const float v = F_U * R0;                        // u0*x0*R0
    float* u0p = &g_uxR[0][0][0];
    for (int k = i; k < NN * BB; k += stride) u0p[k] = v;
    float* ps = &g_partialSumR[0][0][0];
    for (int k = i; k < GRIDSZ * BB; k += stride) ps[k] = (float)NT * R0;
    if (i == 0) g_barCount = 0u;
}

// fence-free grid barrier: bar.sync + release-arrive + acquire-spin (monotonic)
__device__ __forceinline__ void gridSync(int t) {
    __syncthreads();
    if (threadIdx.x == 0) {
        asm volatile("red.release.gpu.global.add.u32 [%0], %1;"
                     :: "l"(&g_barCount), "r"(1u) : "memory");
        const unsigned target = (unsigned)(t + 1) * GRIDSZ;
        unsigned v;
        do {
            asm volatile("ld.acquire.gpu.global.u32 %0, [%1];"
                         : "=r"(v) : "l"(&g_barCount) : "memory");
        } while (v < target);
    }
    __syncthreads();
}

__global__ void __launch_bounds__(NTHR, 1)
step_kernel(const float* __restrict__ inp, const float* __restrict__ W_in,
            const float* __restrict__ J,   const float* __restrict__ W_out,
            float* __restrict__ out)
{
    extern __shared__ float smem[];
    float*  Jt     = smem;                             // [NN][JSTR] transposed J
    float2* redp   = (float2*)(Jt + (size_t)NN * JSTR);// [NSLICE][8 np][PADB]
    float*  sPartA = (float*)(redp + (size_t)NSLICE * 8 * PADB); // [NWARP][BB]
    float*  sPartB = sPartA + NWARP * BB;              // [NWARP][BB]
    float*  shI    = sPartB + NWARP * BB;              // [BB]
    float*  sRI    = shI + BB;                         // [BB]

    float* all_h  = out;
    float* all_u  = out + (size_t)TT * BB * NN;
    float* all_x  = out + (size_t)2 * TT * BB * NN;
    float* all_hI = out + (size_t)3 * TT * BB * NN;
    float* outputs = all_hI + (size_t)TT * BB;

    const int tid  = threadIdx.x;
    const int bid  = blockIdx.x;
    const int warp = tid >> 5;
    const int lane = tid & 31;
    const int strm = lane >> 3;        // 0..3  m-stream within warp
    const int l8   = lane & 7;         // 0..7  -> batches [4*l8, 4*l8+4)
    const int n0   = bid * NT;

    // update-phase mapping: thread -> (batch ub, single neuron n0+un)
    const int ub = tid >> 4;           // 0..31
    const int un = tid & 15;           // 0..15

    const float invTau  = 1.0f / F_TAU;
    const float invTauF = 1.0f / F_TAUF;
    const float invTauD = 1.0f / F_TAUD;

    // ---- stage J transposed ONCE: Jt[m][n_local], row stride JSTR ----
    #pragma unroll 4
    for (int it = 0; it < 16; ++it) {
        int idx = tid + it * NTHR;     // 0..8191 (16 rows * 512 float4)
        int r   = idx >> 9;            // 0..15
        int c4  = idx & 511;           // float4 col (m/4)
        float4 v = *(const float4*)(J + (size_t)(n0 + r) * NN + c4 * 4);
        float* dst = Jt + (size_t)(c4 * 4) * JSTR + r;
        dst[0 * JSTR] = v.x;
        dst[1 * JSTR] = v.y;
        dst[2 * JSTR] = v.z;
        dst[3 * JSTR] = v.w;
    }

    const float wi = W_in[n0 + un];
    const float wo = W_out[n0 + un];

    if (tid < BB) shI[tid] = 0.0f;
    __syncthreads();

    // per-thread state
    float hr = 0.0f, ur = F_U, xr = 1.0f;

    // GEMM: iteration mi processes m = warp*128 + mi*4 + strm
    const int mfirst = warp * 128 + strm;
    const ull ONE2 = pack2(1.0f);

    for (int t = 0; t < TT; ++t) {
        const int cur = t & 1, nxt = cur ^ 1;

        // ===== GEMM: 4 m-streams x 8 lanes x 4 batches x 16 n ===========
        const float* ubaseF = &g_uxR[cur][0][0] + (size_t)mfirst * BB + 4 * l8;

        ull acc[8][4];
        #pragma unroll
        for (int p = 0; p < 8; ++p)
            #pragma unroll
            for (int b = 0; b < 4; ++b) acc[p][b] = 0ull;

        float4 upf[2];
        upf[0] = __ldcg((const float4*)(ubaseF + 0 * 4 * BB));
        upf[1] = __ldcg((const float4*)(ubaseF + 1 * 4 * BB));

        #pragma unroll 4
        for (int mi = 0; mi < 32; ++mi) {
            const float4 u4 = upf[mi & 1];
            if (mi < 30)
                upf[mi & 1] = __ldcg((const float4*)(ubaseF + (size_t)(mi + 2) * 4 * BB));

            const int m = mfirst + mi * 4;
            const ulonglong2* jq = (const ulonglong2*)(Jt + (size_t)m * JSTR);
            ulonglong2 q0 = jq[0];
            ulonglong2 q1 = jq[1];
            ulonglong2 q2 = jq[2];
            ulonglong2 q3 = jq[3];

            const ull ub0 = pack2(u4.x);
            const ull ub1 = pack2(u4.y);
            const ull ub2p = pack2(u4.z);
            const ull ub3 = pack2(u4.w);

            ffma2u(acc[0][0], q0.x, ub0); ffma2u(acc[0][1], q0.x, ub1);
            ffma2u(acc[0][2], q0.x, ub2p); ffma2u(acc[0][3], q0.x, ub3);
            ffma2u(acc[1][0], q0.y, ub0); ffma2u(acc[1][1], q0.y, ub1);
            ffma2u(acc[1][2], q0.y, ub2p); ffma2u(acc[1][3], q0.y, ub3);
            ffma2u(acc[2][0], q1.x, ub0); ffma2u(acc[2][1], q1.x, ub1);
            ffma2u(acc[2][2], q1.x, ub2p); ffma2u(acc[2][3], q1.x, ub3);
            ffma2u(acc[3][0], q1.y, ub0); ffma2u(acc[3][1], q1.y, ub1);
            ffma2u(acc[3][2], q1.y, ub2p); ffma2u(acc[3][3], q1.y, ub3);
            ffma2u(acc[4][0], q2.x, ub0); ffma2u(acc[4][1], q2.x, ub1);
            ffma2u(acc[4][2], q2.x, ub2p); ffma2u(acc[4][3], q2.x, ub3);
            ffma2u(acc[5][0], q2.y, ub0); ffma2u(acc[5][1], q2.y, ub1);
            ffma2u(acc[5][2], q2.y, ub2p); ffma2u(acc[5][3], q2.y, ub3);
            ffma2u(acc[6][0], q3.x, ub0); ffma2u(acc[6][1], q3.x, ub1);
            ffma2u(acc[6][2], q3.x, ub2p); ffma2u(acc[6][3], q3.x, ub3);
            ffma2u(acc[7][0], q3.y, ub0); ffma2u(acc[7][1], q3.y, ub1);
            ffma2u(acc[7][2], q3.y, ub2p); ffma2u(acc[7][3], q3.y, ub3);
        }

        // ----- reduce the 4 streams in-register (same n, same batches) ---
        #pragma unroll
        for (int p = 0; p < 8; ++p)
            #pragma unroll
            for (int b = 0; b < 4; ++b) {
                ull o1 = __shfl_xor_sync(0xFFFFFFFFu, acc[p][b], 8);
                ffma2u(acc[p][b], o1, ONE2);
                ull o2 = __shfl_xor_sync(0xFFFFFFFFu, acc[p][b], 16);
                ffma2u(acc[p][b], o2, ONE2);
            }

        // lanes 0..7 hold full warp partials; store slice = warp
        if (strm == 0) {
            float2* rw = redp + (size_t)warp * 8 * PADB + 4 * l8;
            #pragma unroll
            for (int p = 0; p < 8; ++p) {
                ulonglong2 v0; v0.x = acc[p][0]; v0.y = acc[p][1];
                ulonglong2 v1; v1.x = acc[p][2]; v1.y = acc[p][3];
                *(ulonglong2*)(rw + p * PADB)     = v0;
                *(ulonglong2*)(rw + p * PADB + 2) = v1;
            }
        }

        // -------- C1: cross-CTA reductions of previous step's partials ---
        {
            float sA = 0.0f;
            const float* pS = &g_partialSumR[cur][0][0];
            #pragma unroll
            for (int c = 0; c < 8; ++c) sA += __ldcg(pS + (warp * 8 + c) * BB + lane);
            sPartA[warp * BB + lane] = sA;
            if (bid == 0 && t > 0) {
                float sB = 0.0f;
                const float* pO = &g_partialOut[cur][0][0];
                #pragma unroll
                for (int c = 0; c < 8; ++c) sB += __ldcg(pO + (warp * 8 + c) * BB + lane);
                sPartB[warp * BB + lane] = sB;
            }
        }
        __syncthreads();

        // -------- C2: h_I update (redundant per CTA), readout store ------
        if (tid < BB) {
            float tot = 0.0f;
            #pragma unroll
            for (int w = 0; w < NWARP; ++w) tot += sPartA[w * BB + tid];
            float hIold = shI[tid];
            sRI[tid] = rate_fn(hIold);
            float hI2 = hIold + (-hIold + F_JIE * tot) * invTau * F_DT;
            shI[tid] = hI2;
            if (bid == 0) {
                all_hI[(size_t)t * BB + tid] = hI2;
                if (t > 0) {
                    float totB = 0.0f;
                    #pragma unroll
                    for (int w = 0; w < NWARP; ++w) totB += sPartB[w * BB + tid];
                    outputs[(size_t)(t - 1) * BB + tid] = totB;
                }
            }
        }
        __syncthreads();

        // -------- C3: state update, outputs, next-step uxR/partials ------
        {
            const int p = un >> 1, r = un & 1;
            float syn = 0.0f;
            const float2* rr = redp + (size_t)p * PADB + ub;
            if (r == 0) {
                #pragma unroll
                for (int s = 0; s < NSLICE; ++s) syn += rr[(size_t)s * 8 * PADB].x;
            } else {
                #pragma unroll
                for (int s = 0; s < NSLICE; ++s) syn += rr[(size_t)s * 8 * PADB].y;
            }

            float RI = sRI[ub];
            float inval = inp[(size_t)t * BB + ub];
            float R = rate_fn(hr);

            float h2 = hr + ((-hr + syn + F_IB + inval * wi) - F_JEI * RI) * invTau * F_DT;
            float u2 = ur + ((F_U - ur) * invTauF + F_U * (1.0f - ur) * R) * F_DT;
            float x2 = xr + ((1.0f - xr) * invTauD - ur * xr * R) * F_DT;

            size_t o = (size_t)t * (BB * NN) + (size_t)ub * NN + (n0 + un);
            all_h[o] = h2;
            all_u[o] = u2;
            all_x[o] = x2;

            float R2 = rate_fn(h2);
            g_uxR[nxt][n0 + un][ub] = u2 * x2 * R2;

            float sR = R2;
            float sO = R2 * wo;
            #pragma unroll
            for (int d = 8; d > 0; d >>= 1) {
                sR += __shfl_xor_sync(0xFFFFFFFFu, sR, d, 16);
                sO += __shfl_xor_sync(0xFFFFFFFFu, sO, d, 16);
            }
            if ((tid & 15) == 0) {
                g_partialSumR[nxt][bid][ub] = sR;
                g_partialOut[nxt][bid][ub]  = sO;
            }

            hr = h2; ur = u2; xr = x2;
        }

        gridSync(t);
    }

    // -------- epilogue: readout for the final step (buffer 0 = nxt(511)) -
    if (bid == 0) {
        float sB = 0.0f;
        const float* pO = &g_partialOut[0][0][0];
        #pragma unroll
        for (int c = 0; c < 8; ++c) sB += __ldcg(pO + (warp * 8 + c) * BB + lane);
        sPartB[warp * BB + lane] = sB;
        __syncthreads();
        if (tid < BB) {
            float tot = 0.0f;
            #pragma unroll
            for (int w = 0; w < NWARP; ++w) tot += sPartB[w * BB + tid];
            outputs[(size_t)(TT - 1) * BB + tid] = tot;
        }
    }
}

#define SMEM_BYTES ((NN * JSTR) * 4 + (NSLICE * 8 * PADB) * 8 + (NWARP * BB * 2 + BB * 2) * 4)

extern "C" void kernel_launch(void* const* d_in, const int* in_sizes, int n_in,
                              void* d_out, int out_size) {
    const float* inp   = (const float*)d_in[0];
    const float* W_in  = (const float*)d_in[1];
    const float* J     = (const float*)d_in[2];
    const float* W_out = (const float*)d_in[3];
    float* out = (float*)d_out;

    cudaFuncSetAttribute(step_kernel, cudaFuncAttributeMaxDynamicSharedMemorySize,
                         SMEM_BYTES);
    init_kernel<<<64, 256>>>();
    step_kernel<<<GRIDSZ, NTHR, SMEM_BYTES>>>(inp, W_in, J, W_out, out);
}